// round 2
// baseline (speedup 1.0000x reference)
#include <cuda_runtime.h>

#define NNODE 100000
#define NEDGE 1600000
#define ETOT  1700000   // NEDGE + NNODE self loops

// ---------------- scratch (device globals; no allocation allowed) ----------
__device__ float g_h  [NNODE * 128];   // per-layer projected features
__device__ float g_o  [NNODE * 128];   // per-layer aggregated output
__device__ float g_als[NNODE * 2];     // per-node src logits
__device__ float g_ald[NNODE * 2];     // per-node dst logits
__device__ float g_z  [NNODE * 2];     // softmax denominators
__device__ float g_ex [ETOT * 2];      // exp(e) per edge per head
__device__ int   g_src[ETOT];
__device__ int   g_dst[ETOT];

// ---------------- edge index conversion (int32 input, + self loops) --------
// NOTE: JAX default config has x64 disabled, so edge_index arrives as int32.
__global__ void convert_edges(const int* __restrict__ ei) {
    int i = blockIdx.x * blockDim.x + threadIdx.x;
    if (i >= ETOT) return;
    if (i < NEDGE) {
        g_src[i] = ei[i];
        g_dst[i] = ei[NEDGE + i];
    } else {
        int n = i - NEDGE;
        g_src[i] = n;
        g_dst[i] = n;
    }
}

// ---------------- zero / init helpers --------------------------------------
__global__ void zero_kernel(float4* __restrict__ p, int n4) {
    int i = blockIdx.x * blockDim.x + threadIdx.x;
    if (i < n4) p[i] = make_float4(0.f, 0.f, 0.f, 0.f);
}

__global__ void init_out(float4* __restrict__ out, const float4* __restrict__ b3) {
    int i = blockIdx.x * blockDim.x + threadIdx.x;
    if (i < NNODE * 16) out[i] = b3[i & 15];   // 64 floats = 16 float4 per row
}

// ---------------- fused GEMM + attention-logit epilogue --------------------
// h = act(X) @ W  (act = relu(x + bias) if TRANS), writes g_h, g_als, g_ald.
// BM=128 rows/block, full K=128 and full NOUT in smem, 8x8 (or 4x8) reg tile.
template <int NOUT, bool TRANS>
__global__ __launch_bounds__(256) void gemm_al(
    const float* __restrict__ X, const float* __restrict__ W,
    const float* __restrict__ asrc, const float* __restrict__ adst,
    const float* __restrict__ bias)
{
    constexpr int H   = NOUT / 64;
    constexpr int TX  = NOUT / 8;    // 16 (NOUT=128) or 8 (NOUT=64)
    constexpr int TY  = 256 / TX;    // 16 or 32
    constexpr int RPT = 128 / TY;    // 8 or 4 rows per thread

    extern __shared__ float sm[];
    float* xs  = sm;                    // 128 x 128
    float* ws  = sm + 128 * 128;        // 128 x NOUT
    float* as_ = ws + 128 * NOUT;       // NOUT
    float* ad_ = as_ + NOUT;            // NOUT
    float* bs  = ad_ + NOUT;            // 128

    const int tid = threadIdx.x;
    if (tid < NOUT) { as_[tid] = asrc[tid]; ad_[tid] = adst[tid]; }
    if (TRANS && tid < 128) bs[tid] = bias[tid];
    __syncthreads();

    // W -> smem (row-major [k][c], same layout)
    const float4* W4  = (const float4*)W;
    float4*       ws4 = (float4*)ws;
    #pragma unroll
    for (int i = tid; i < 128 * NOUT / 4; i += 256) ws4[i] = W4[i];

    // X tile -> smem with fused relu(x + b)
    const int n0  = blockIdx.x * 128;
    float4*   xs4 = (float4*)xs;
    #pragma unroll
    for (int i = tid; i < 128 * 32; i += 256) {
        int r  = i >> 5, k4 = i & 31;
        int n  = n0 + r;
        float4 v = make_float4(0.f, 0.f, 0.f, 0.f);
        if (n < NNODE) {
            v = ((const float4*)X)[n * 32 + k4];
            if (TRANS) {
                v.x = fmaxf(v.x + bs[k4 * 4 + 0], 0.f);
                v.y = fmaxf(v.y + bs[k4 * 4 + 1], 0.f);
                v.z = fmaxf(v.z + bs[k4 * 4 + 2], 0.f);
                v.w = fmaxf(v.w + bs[k4 * 4 + 3], 0.f);
            }
        }
        xs4[i] = v;
    }
    __syncthreads();

    const int ty = tid / TX, tx = tid % TX;
    float acc[RPT][8];
    #pragma unroll
    for (int j = 0; j < RPT; j++)
        #pragma unroll
        for (int i = 0; i < 8; i++) acc[j][i] = 0.f;

    #pragma unroll 4
    for (int k = 0; k < 128; k++) {
        float4 b0 = ws4[k * (NOUT / 4) + tx * 2];
        float4 b1 = ws4[k * (NOUT / 4) + tx * 2 + 1];
        float a[RPT];
        #pragma unroll
        for (int j = 0; j < RPT; j++) a[j] = xs[(ty + TY * j) * 128 + k];
        #pragma unroll
        for (int j = 0; j < RPT; j++) {
            acc[j][0] = fmaf(a[j], b0.x, acc[j][0]);
            acc[j][1] = fmaf(a[j], b0.y, acc[j][1]);
            acc[j][2] = fmaf(a[j], b0.z, acc[j][2]);
            acc[j][3] = fmaf(a[j], b0.w, acc[j][3]);
            acc[j][4] = fmaf(a[j], b1.x, acc[j][4]);
            acc[j][5] = fmaf(a[j], b1.y, acc[j][5]);
            acc[j][6] = fmaf(a[j], b1.z, acc[j][6]);
            acc[j][7] = fmaf(a[j], b1.w, acc[j][7]);
        }
    }

    // Epilogue: write h, and reduce al_s/al_d per (row, head) via shfl.
    #pragma unroll
    for (int j = 0; j < RPT; j++) {
        float ss = 0.f, sd = 0.f;
        #pragma unroll
        for (int i = 0; i < 8; i++) {
            ss = fmaf(acc[j][i], as_[tx * 8 + i], ss);
            sd = fmaf(acc[j][i], ad_[tx * 8 + i], sd);
        }
        #pragma unroll
        for (int o = 4; o > 0; o >>= 1) {
            ss += __shfl_xor_sync(0xffffffffu, ss, o);
            sd += __shfl_xor_sync(0xffffffffu, sd, o);
        }
        int n = n0 + ty + TY * j;
        if (n < NNODE) {
            if ((tx & 7) == 0) {
                int head = (TX == 16) ? (tx >> 3) : 0;
                g_als[n * H + head] = ss;
                g_ald[n * H + head] = sd;
            }
            float4 v0 = make_float4(acc[j][0], acc[j][1], acc[j][2], acc[j][3]);
            float4 v1 = make_float4(acc[j][4], acc[j][5], acc[j][6], acc[j][7]);
            float4* hp = (float4*)&g_h[n * NOUT + tx * 8];
            hp[0] = v0; hp[1] = v1;
        }
    }
}

// ---------------- edge pass 1: e -> leakyrelu -> exp -> z ------------------
// Softmax max-subtraction is skipped: weights are 0.05-scale, |e| < ~5, so
// exp(e) is numerically safe and alpha = exp(e)/sum(exp) is mathematically
// identical to the max-shifted reference.
template <int H>
__global__ void edge_pass1() {
    int i = blockIdx.x * blockDim.x + threadIdx.x;
    if (i >= ETOT) return;
    int s = g_src[i], d = g_dst[i];
    if (H == 2) {
        float2 es = ((const float2*)g_als)[s];
        float2 ed = ((const float2*)g_ald)[d];
        float e0 = es.x + ed.x; e0 = e0 > 0.f ? e0 : 0.2f * e0;
        float e1 = es.y + ed.y; e1 = e1 > 0.f ? e1 : 0.2f * e1;
        float x0 = __expf(e0), x1 = __expf(e1);
        ((float2*)g_ex)[i] = make_float2(x0, x1);
        atomicAdd(&g_z[d * 2 + 0], x0);
        atomicAdd(&g_z[d * 2 + 1], x1);
    } else {
        float e = g_als[s] + g_ald[d];
        e = e > 0.f ? e : 0.2f * e;
        float xv = __expf(e);
        g_ex[i] = xv;
        atomicAdd(&g_z[d], xv);
    }
}

// ---------------- edge pass 2: out[dst] += alpha * h[src] ------------------
// One warp per edge; vector reductions (red.add.v4/v2) to minimize LSU issue.
__global__ void edge_pass2_128(float* __restrict__ out) {
    int w    = (blockIdx.x * blockDim.x + threadIdx.x) >> 5;
    int lane = threadIdx.x & 31;
    if (w >= ETOT) return;
    int s = g_src[w], d = g_dst[w];
    int head = lane >> 4;
    float alpha = 0.f;
    if ((lane & 15) == 0)
        alpha = __fdividef(g_ex[(size_t)w * 2 + head], g_z[d * 2 + head]);
    alpha = __shfl_sync(0xffffffffu, alpha, head << 4);
    float4 hv = ((const float4*)g_h)[(size_t)s * 32 + lane];
    float4 m  = make_float4(hv.x * alpha, hv.y * alpha, hv.z * alpha, hv.w * alpha);
    float* p  = out + (size_t)d * 128 + lane * 4;
    asm volatile("red.global.add.v4.f32 [%0], {%1,%2,%3,%4};"
                 :: "l"(p), "f"(m.x), "f"(m.y), "f"(m.z), "f"(m.w) : "memory");
}

__global__ void edge_pass2_64(float* __restrict__ out) {
    int w    = (blockIdx.x * blockDim.x + threadIdx.x) >> 5;
    int lane = threadIdx.x & 31;
    if (w >= ETOT) return;
    int s = g_src[w], d = g_dst[w];
    float alpha = 0.f;
    if (lane == 0) alpha = __fdividef(g_ex[w], g_z[d]);
    alpha = __shfl_sync(0xffffffffu, alpha, 0);
    float2 hv = ((const float2*)g_h)[(size_t)s * 32 + lane];
    float2 m  = make_float2(hv.x * alpha, hv.y * alpha);
    float* p  = out + (size_t)d * 64 + lane * 2;
    asm volatile("red.global.add.v2.f32 [%0], {%1,%2};"
                 :: "l"(p), "f"(m.x), "f"(m.y) : "memory");
}

// ---------------- launcher --------------------------------------------------
extern "C" void kernel_launch(void* const* d_in, const int* in_sizes, int n_in,
                              void* d_out, int out_size)
{
    const float* x   = (const float*)d_in[0];
    const int*   ei  = (const int*)d_in[1];     // int32: JAX x64 disabled
    const float* W1  = (const float*)d_in[2];
    const float* as1 = (const float*)d_in[3];
    const float* ad1 = (const float*)d_in[4];
    const float* b1  = (const float*)d_in[5];
    const float* W2  = (const float*)d_in[6];
    const float* as2 = (const float*)d_in[7];
    const float* ad2 = (const float*)d_in[8];
    const float* b2  = (const float*)d_in[9];
    const float* W3  = (const float*)d_in[10];
    const float* as3 = (const float*)d_in[11];
    const float* ad3 = (const float*)d_in[12];
    const float* b3  = (const float*)d_in[13];
    float* out = (float*)d_out;

    float *o_p, *z_p;
    cudaGetSymbolAddress((void**)&o_p, g_o);
    cudaGetSymbolAddress((void**)&z_p, g_z);

    size_t sm128 = (size_t)(128 * 128 + 128 * 128 + 2 * 128 + 128) * sizeof(float);
    size_t sm64  = (size_t)(128 * 128 + 128 * 64  + 2 * 64  + 128) * sizeof(float);
    cudaFuncSetAttribute(gemm_al<128, false>, cudaFuncAttributeMaxDynamicSharedMemorySize, (int)sm128);
    cudaFuncSetAttribute(gemm_al<128, true >, cudaFuncAttributeMaxDynamicSharedMemorySize, (int)sm128);
    cudaFuncSetAttribute(gemm_al<64,  true >, cudaFuncAttributeMaxDynamicSharedMemorySize, (int)sm64);

    const int GB = (NNODE + 127) / 128;                        // 782 blocks
    const int EB = (ETOT + 255) / 256;
    const int WB = (int)(((long long)ETOT * 32 + 255) / 256);  // warp per edge

    convert_edges<<<EB, 256>>>(ei);

    // ---- layer 1: x -> h1 (H=2 concat) ----
    gemm_al<128, false><<<GB, 256, sm128>>>(x, W1, as1, ad1, nullptr);
    zero_kernel<<<(NNODE * 2 / 4 + 255) / 256, 256>>>((float4*)z_p, NNODE * 2 / 4);
    zero_kernel<<<(NNODE * 32 + 255) / 256, 256>>>((float4*)o_p, NNODE * 32);
    edge_pass1<2><<<EB, 256>>>();
    edge_pass2_128<<<WB, 256>>>(o_p);

    // ---- layer 2: relu(o1+b1) -> h2 (H=2 concat) ----
    gemm_al<128, true><<<GB, 256, sm128>>>(o_p, W2, as2, ad2, b1);
    zero_kernel<<<(NNODE * 2 / 4 + 255) / 256, 256>>>((float4*)z_p, NNODE * 2 / 4);
    zero_kernel<<<(NNODE * 32 + 255) / 256, 256>>>((float4*)o_p, NNODE * 32);
    edge_pass1<2><<<EB, 256>>>();
    edge_pass2_128<<<WB, 256>>>(o_p);

    // ---- layer 3: relu(o2+b2) -> h3 (H=1, mean == identity), out = seg + b3 ----
    gemm_al<64, true><<<GB, 256, sm64>>>(o_p, W3, as3, ad3, b2);
    zero_kernel<<<(NNODE / 4 + 255) / 256, 256>>>((float4*)z_p, NNODE / 4);
    init_out<<<(NNODE * 16 + 255) / 256, 256>>>((float4*)out, (const float4*)b3);
    edge_pass1<1><<<EB, 256>>>();
    edge_pass2_64<<<WB, 256>>>(out);
}

// round 3
// speedup vs baseline: 1.8650x; 1.8650x over previous
#include <cuda_runtime.h>

#define NNODE 100000
#define NEDGE 1600000
#define ETOT  1700000   // NEDGE + NNODE self loops
#define NBLK  98        // ceil(NNODE / 1024) for the scan

// ---------------- scratch (device globals; no allocation allowed) ----------
__device__ float g_h  [NNODE * 128];   // per-layer projected features
__device__ float g_o  [NNODE * 128];   // per-layer aggregated output
__device__ float g_als[NNODE * 2];     // per-node src logits
__device__ float g_ald[NNODE * 2];     // per-node dst logits
__device__ int   g_cnt [NNODE];        // histogram / scatter counters
__device__ int   g_ptr [NNODE + 1];    // CSR row pointers (by dst)
__device__ int   g_bsum[128];          // scan block sums
__device__ int   g_ssrc[ETOT];         // src ids sorted by dst

// ---------------- f32x2 packed-FMA helpers (sm_103a) ------------------------
typedef unsigned long long u64;
__device__ __forceinline__ u64 splat2(float v) {
    u64 r; asm("mov.b64 %0, {%1, %1};" : "=l"(r) : "f"(v)); return r;
}
__device__ __forceinline__ void ffma2(u64& d, u64 a, u64 b) {
    asm("fma.rn.f32x2 %0, %1, %2, %0;" : "+l"(d) : "l"(a), "l"(b));
}
__device__ __forceinline__ float2 unpack2(u64 v) {
    float2 f; asm("mov.b64 {%0, %1}, %2;" : "=f"(f.x), "=f"(f.y) : "l"(v)); return f;
}

// ---------------- generic zero ----------------------------------------------
__global__ void zero_kernel(float4* __restrict__ p, int n4) {
    int i = blockIdx.x * blockDim.x + threadIdx.x;
    if (i < n4) p[i] = make_float4(0.f, 0.f, 0.f, 0.f);
}

// ---------------- CSR build: hist -> scan -> scatter ------------------------
__global__ void hist_kernel(const int* __restrict__ ei) {
    int i = blockIdx.x * blockDim.x + threadIdx.x;
    if (i >= ETOT) return;
    int d = (i < NEDGE) ? ei[NEDGE + i] : (i - NEDGE);
    atomicAdd(&g_cnt[d], 1);
}

__global__ __launch_bounds__(256) void scan1_kernel() {
    __shared__ int warp_tot[8];
    __shared__ int wofs[8];
    int b = blockIdx.x, t = threadIdx.x;
    int gi = b * 1024 + t * 4;
    int c0 = (gi     < NNODE) ? g_cnt[gi]     : 0;
    int c1 = (gi + 1 < NNODE) ? g_cnt[gi + 1] : 0;
    int c2 = (gi + 2 < NNODE) ? g_cnt[gi + 2] : 0;
    int c3 = (gi + 3 < NNODE) ? g_cnt[gi + 3] : 0;
    int ts = c0 + c1 + c2 + c3;
    int lane = t & 31, wid = t >> 5;
    int inc = ts;
    #pragma unroll
    for (int o = 1; o < 32; o <<= 1) {
        int v = __shfl_up_sync(0xffffffffu, inc, o);
        if (lane >= o) inc += v;
    }
    if (lane == 31) warp_tot[wid] = inc;
    __syncthreads();
    if (t == 0) {
        int acc = 0;
        #pragma unroll
        for (int w = 0; w < 8; w++) { wofs[w] = acc; acc += warp_tot[w]; }
        g_bsum[b] = acc;
    }
    __syncthreads();
    int base = wofs[wid] + inc - ts;   // exclusive offset within block
    if (gi     < NNODE) g_ptr[gi]     = base;
    if (gi + 1 < NNODE) g_ptr[gi + 1] = base + c0;
    if (gi + 2 < NNODE) g_ptr[gi + 2] = base + c0 + c1;
    if (gi + 3 < NNODE) g_ptr[gi + 3] = base + c0 + c1 + c2;
}

__global__ void scan2_kernel() {
    __shared__ int s[128];
    int t = threadIdx.x;
    int v = (t < NBLK) ? g_bsum[t] : 0;
    s[t] = v;
    __syncthreads();
    #pragma unroll
    for (int o = 1; o < 128; o <<= 1) {
        int u = (t >= o) ? s[t - o] : 0;
        __syncthreads();
        s[t] += u;
        __syncthreads();
    }
    if (t < NBLK) g_bsum[t] = s[t] - v;   // exclusive
}

__global__ void scan3_kernel() {
    int i = blockIdx.x * blockDim.x + threadIdx.x;
    if (i < NNODE) g_ptr[i] += g_bsum[i >> 10];
    if (i == 0) g_ptr[NNODE] = ETOT;
}

__global__ void scatter_kernel(const int* __restrict__ ei) {
    int i = blockIdx.x * blockDim.x + threadIdx.x;
    if (i >= ETOT) return;
    int s, d;
    if (i < NEDGE) { s = ei[i]; d = ei[NEDGE + i]; }
    else           { s = d = i - NEDGE; }
    int pos = g_ptr[d] + atomicAdd(&g_cnt[d], 1);
    g_ssrc[pos] = s;
}

// ---------------- fused GEMM + attention-logit epilogue (FFMA2) -------------
// h = act(X) @ W  (act = relu(x + bias) if TRANS), writes g_h, g_als, g_ald.
template <int NOUT, bool TRANS>
__global__ __launch_bounds__(256) void gemm_al(
    const float* __restrict__ X, const float* __restrict__ W,
    const float* __restrict__ asrc, const float* __restrict__ adst,
    const float* __restrict__ bias)
{
    constexpr int H   = NOUT / 64;
    constexpr int TX  = NOUT / 8;    // 16 (NOUT=128) or 8 (NOUT=64)
    constexpr int TY  = 256 / TX;    // 16 or 32
    constexpr int RPT = 128 / TY;    // 8 or 4 rows per thread

    extern __shared__ float sm[];
    float* xs  = sm;                    // 128 x 128
    float* ws  = sm + 128 * 128;        // 128 x NOUT
    float* as_ = ws + 128 * NOUT;       // NOUT
    float* ad_ = as_ + NOUT;            // NOUT
    float* bs  = ad_ + NOUT;            // 128

    const int tid = threadIdx.x;
    if (tid < NOUT) { as_[tid] = asrc[tid]; ad_[tid] = adst[tid]; }
    if (TRANS && tid < 128) bs[tid] = bias[tid];
    __syncthreads();

    // W -> smem (row-major [k][c])
    const float4* W4  = (const float4*)W;
    float4*       ws4 = (float4*)ws;
    #pragma unroll
    for (int i = tid; i < 128 * NOUT / 4; i += 256) ws4[i] = W4[i];

    // X tile -> smem with fused relu(x + b)
    const int n0  = blockIdx.x * 128;
    float4*   xs4 = (float4*)xs;
    #pragma unroll
    for (int i = tid; i < 128 * 32; i += 256) {
        int r  = i >> 5, k4 = i & 31;
        int n  = n0 + r;
        float4 v = make_float4(0.f, 0.f, 0.f, 0.f);
        if (n < NNODE) {
            v = ((const float4*)X)[n * 32 + k4];
            if (TRANS) {
                v.x = fmaxf(v.x + bs[k4 * 4 + 0], 0.f);
                v.y = fmaxf(v.y + bs[k4 * 4 + 1], 0.f);
                v.z = fmaxf(v.z + bs[k4 * 4 + 2], 0.f);
                v.w = fmaxf(v.w + bs[k4 * 4 + 3], 0.f);
            }
        }
        xs4[i] = v;
    }
    __syncthreads();

    const int ty = tid / TX, tx = tid % TX;
    u64 accp[RPT][4];
    #pragma unroll
    for (int j = 0; j < RPT; j++)
        #pragma unroll
        for (int i = 0; i < 4; i++) accp[j][i] = 0ull;

    const u64* wsu = (const u64*)ws;
    #pragma unroll 4
    for (int k = 0; k < 128; k++) {
        const u64* wr = wsu + k * (NOUT / 2) + tx * 4;
        ulonglong2 b01 = ((const ulonglong2*)wr)[0];
        ulonglong2 b23 = ((const ulonglong2*)wr)[1];
        #pragma unroll
        for (int j = 0; j < RPT; j++) {
            u64 a2 = splat2(xs[(ty + TY * j) * 128 + k]);
            ffma2(accp[j][0], a2, b01.x);
            ffma2(accp[j][1], a2, b01.y);
            ffma2(accp[j][2], a2, b23.x);
            ffma2(accp[j][3], a2, b23.y);
        }
    }

    // Epilogue: write h, and reduce al_s/al_d per (row, head) via shfl.
    #pragma unroll
    for (int j = 0; j < RPT; j++) {
        float c[8];
        #pragma unroll
        for (int i = 0; i < 4; i++) {
            float2 f = unpack2(accp[j][i]);
            c[2 * i] = f.x; c[2 * i + 1] = f.y;
        }
        float ss = 0.f, sd = 0.f;
        #pragma unroll
        for (int i = 0; i < 8; i++) {
            ss = fmaf(c[i], as_[tx * 8 + i], ss);
            sd = fmaf(c[i], ad_[tx * 8 + i], sd);
        }
        #pragma unroll
        for (int o = 4; o > 0; o >>= 1) {
            ss += __shfl_xor_sync(0xffffffffu, ss, o);
            sd += __shfl_xor_sync(0xffffffffu, sd, o);
        }
        int n = n0 + ty + TY * j;
        if (n < NNODE) {
            if ((tx & 7) == 0) {
                int head = (TX == 16) ? (tx >> 3) : 0;
                g_als[n * H + head] = ss;
                g_ald[n * H + head] = sd;
            }
            float4* hp = (float4*)&g_h[n * NOUT + tx * 8];
            hp[0] = make_float4(c[0], c[1], c[2], c[3]);
            hp[1] = make_float4(c[4], c[5], c[6], c[7]);
        }
    }
}

// ---------------- fused per-dst softmax + aggregation (warp per node) -------
// Phase A: z = sum over in-edges of exp(leakyrelu(als[src]+ald[dst]))
// Phase B: out[dst] = sum alpha * h[src], alpha recomputed (no g_ex round-trip)
// Max-subtraction skipped: weights 0.05-scale => |e| small, exp() safe; result
// identical to the max-shifted reference.
__global__ __launch_bounds__(256) void agg128(const float* __restrict__ hsrc,
                                              float* __restrict__ out) {
    int d    = (blockIdx.x * 256 + threadIdx.x) >> 5;
    int lane = threadIdx.x & 31;
    if (d >= NNODE) return;
    int p0 = g_ptr[d], p1 = g_ptr[d + 1];
    float2 ad = ((const float2*)g_ald)[d];
    float z0 = 0.f, z1 = 0.f;
    for (int p = p0 + lane; p < p1; p += 32) {
        int s = g_ssrc[p];
        float2 as = ((const float2*)g_als)[s];
        float e0 = as.x + ad.x; e0 = e0 > 0.f ? e0 : 0.2f * e0;
        float e1 = as.y + ad.y; e1 = e1 > 0.f ? e1 : 0.2f * e1;
        z0 += __expf(e0); z1 += __expf(e1);
    }
    #pragma unroll
    for (int o = 16; o; o >>= 1) {
        z0 += __shfl_xor_sync(0xffffffffu, z0, o);
        z1 += __shfl_xor_sync(0xffffffffu, z1, o);
    }
    int   head = lane >> 4;                 // cols 0-63 head0, 64-127 head1
    float rz   = __fdividef(1.f, head ? z1 : z0);
    float adh  = head ? ad.y : ad.x;

    float4 acc = make_float4(0.f, 0.f, 0.f, 0.f);
    int s = g_ssrc[p0];                     // p1 > p0 always (self loop)
    for (int p = p0; p < p1; p++) {
        int sn = (p + 1 < p1) ? g_ssrc[p + 1] : 0;
        float2 as = ((const float2*)g_als)[s];
        float e = (head ? as.y : as.x) + adh;
        e = e > 0.f ? e : 0.2f * e;
        float alpha = __expf(e) * rz;
        float4 hv = ((const float4*)hsrc)[(size_t)s * 32 + lane];
        acc.x = fmaf(alpha, hv.x, acc.x);
        acc.y = fmaf(alpha, hv.y, acc.y);
        acc.z = fmaf(alpha, hv.z, acc.z);
        acc.w = fmaf(alpha, hv.w, acc.w);
        s = sn;
    }
    ((float4*)out)[(size_t)d * 32 + lane] = acc;
}

__global__ __launch_bounds__(256) void agg64(const float* __restrict__ hsrc,
                                             float* __restrict__ out,
                                             const float* __restrict__ b3) {
    int d    = (blockIdx.x * 256 + threadIdx.x) >> 5;
    int lane = threadIdx.x & 31;
    if (d >= NNODE) return;
    int p0 = g_ptr[d], p1 = g_ptr[d + 1];
    float adv = g_ald[d];
    float z = 0.f;
    for (int p = p0 + lane; p < p1; p += 32) {
        int s = g_ssrc[p];
        float e = g_als[s] + adv;
        e = e > 0.f ? e : 0.2f * e;
        z += __expf(e);
    }
    #pragma unroll
    for (int o = 16; o; o >>= 1) z += __shfl_xor_sync(0xffffffffu, z, o);
    float rz = __fdividef(1.f, z);

    float2 acc = make_float2(0.f, 0.f);
    int s = g_ssrc[p0];
    for (int p = p0; p < p1; p++) {
        int sn = (p + 1 < p1) ? g_ssrc[p + 1] : 0;
        float e = g_als[s] + adv;
        e = e > 0.f ? e : 0.2f * e;
        float alpha = __expf(e) * rz;
        float2 hv = ((const float2*)hsrc)[(size_t)s * 32 + lane];
        acc.x = fmaf(alpha, hv.x, acc.x);
        acc.y = fmaf(alpha, hv.y, acc.y);
        s = sn;
    }
    float2 bv = ((const float2*)b3)[lane];
    ((float2*)out)[(size_t)d * 32 + lane] = make_float2(acc.x + bv.x, acc.y + bv.y);
}

// ---------------- launcher --------------------------------------------------
extern "C" void kernel_launch(void* const* d_in, const int* in_sizes, int n_in,
                              void* d_out, int out_size)
{
    const float* x   = (const float*)d_in[0];
    const int*   ei  = (const int*)d_in[1];     // int32: JAX x64 disabled
    const float* W1  = (const float*)d_in[2];
    const float* as1 = (const float*)d_in[3];
    const float* ad1 = (const float*)d_in[4];
    const float* b1  = (const float*)d_in[5];
    const float* W2  = (const float*)d_in[6];
    const float* as2 = (const float*)d_in[7];
    const float* ad2 = (const float*)d_in[8];
    const float* b2  = (const float*)d_in[9];
    const float* W3  = (const float*)d_in[10];
    const float* as3 = (const float*)d_in[11];
    const float* ad3 = (const float*)d_in[12];
    const float* b3  = (const float*)d_in[13];
    float* out = (float*)d_out;

    float *o_p, *h_p; int* cnt_p;
    cudaGetSymbolAddress((void**)&o_p,   g_o);
    cudaGetSymbolAddress((void**)&h_p,   g_h);
    cudaGetSymbolAddress((void**)&cnt_p, g_cnt);

    size_t sm128 = (size_t)(128 * 128 + 128 * 128 + 2 * 128 + 128) * sizeof(float);
    size_t sm64  = (size_t)(128 * 128 + 128 * 64  + 2 * 64  + 128) * sizeof(float);
    cudaFuncSetAttribute(gemm_al<128, false>, cudaFuncAttributeMaxDynamicSharedMemorySize, (int)sm128);
    cudaFuncSetAttribute(gemm_al<128, true >, cudaFuncAttributeMaxDynamicSharedMemorySize, (int)sm128);
    cudaFuncSetAttribute(gemm_al<64,  true >, cudaFuncAttributeMaxDynamicSharedMemorySize, (int)sm64);

    const int GB = (NNODE + 127) / 128;         // 782
    const int EB = (ETOT + 255) / 256;
    const int AB = NNODE / 8;                   // 12500, warp per node

    // ---- CSR build (by dst) ----
    zero_kernel<<<(NNODE / 4 + 255) / 256, 256>>>((float4*)cnt_p, NNODE / 4);
    hist_kernel<<<EB, 256>>>(ei);
    scan1_kernel<<<NBLK, 256>>>();
    scan2_kernel<<<1, 128>>>();
    scan3_kernel<<<(NNODE + 255) / 256, 256>>>();
    zero_kernel<<<(NNODE / 4 + 255) / 256, 256>>>((float4*)cnt_p, NNODE / 4);
    scatter_kernel<<<EB, 256>>>(ei);

    // ---- layer 1: x -> h1 (H=2 concat) ----
    gemm_al<128, false><<<GB, 256, sm128>>>(x, W1, as1, ad1, nullptr);
    agg128<<<AB, 256>>>(h_p, o_p);

    // ---- layer 2: relu(o1+b1) -> h2 (H=2 concat) ----
    gemm_al<128, true><<<GB, 256, sm128>>>(o_p, W2, as2, ad2, b1);
    agg128<<<AB, 256>>>(h_p, o_p);

    // ---- layer 3: relu(o2+b2) -> h3 (H=1, mean == identity), + b3 ----
    gemm_al<64, true><<<GB, 256, sm64>>>(o_p, W3, as3, ad3, b2);
    agg64<<<AB, 256>>>(h_p, out, b3);
}